// round 1
// baseline (speedup 1.0000x reference)
#include <cuda_runtime.h>
#include <cstdint>
#include <math.h>

#define NBIN 65536
#define MAXB 16
#define TPB 256
#define PPT 4

// Scratch (device globals; no allocation allowed)
__device__ unsigned g_hist1[MAXB * NBIN];
__device__ unsigned g_hist2[MAXB * NBIN];
__device__ unsigned g_bucket1[MAXB];
__device__ unsigned g_rank1[MAXB];
__device__ unsigned g_kthkey[MAXB];

__device__ __forceinline__ unsigned f2key(float s) {
    unsigned u = __float_as_uint(s);
    // monotone bijection: larger float -> larger unsigned key
    return (u & 0x80000000u) ? ~u : (u | 0x80000000u);
}

__global__ void zero_kernel() {
    unsigned i = blockIdx.x * blockDim.x + threadIdx.x;  // i < MAXB*NBIN/4
    uint4 z = make_uint4(0u, 0u, 0u, 0u);
    reinterpret_cast<uint4*>(g_hist1)[i] = z;
    reinterpret_cast<uint4*>(g_hist2)[i] = z;
}

__global__ void hist1_kernel(const float* __restrict__ scores,
                             const int* __restrict__ bids, int N) {
    int i = blockIdx.x * blockDim.x + threadIdx.x;
    if (i >= N) return;
    unsigned b = (unsigned)bids[i];
    if (b >= MAXB) return;
    unsigned key = f2key(scores[i]);
    atomicAdd(&g_hist1[b * NBIN + (key >> 16)], 1u);
}

__global__ void hist2_kernel(const float* __restrict__ scores,
                             const int* __restrict__ bids, int N) {
    int i = blockIdx.x * blockDim.x + threadIdx.x;
    if (i >= N) return;
    unsigned b = (unsigned)bids[i];
    if (b >= MAXB) return;
    unsigned key = f2key(scores[i]);
    if ((key >> 16) == g_bucket1[b])
        atomicAdd(&g_hist2[b * NBIN + (key & 0xFFFFu)], 1u);
}

// level 1: find 16-bit bucket containing the k-th largest, and residual rank.
// level 2: within that bucket, find exact low-16 bits -> full 32-bit kth key.
__global__ void scan_kernel(const int* nb_ptr, const int* k_ptr, int level) {
    int B = nb_ptr ? *nb_ptr : 8;
    int b = blockIdx.x;
    if (b >= B) return;
    const unsigned* h = (level == 1 ? g_hist1 : g_hist2) + (size_t)b * NBIN;
    unsigned target = (level == 1) ? (unsigned)(k_ptr ? *k_ptr : 8192) : g_rank1[b];

    __shared__ unsigned chunk[256];
    __shared__ unsigned sbin[256];
    __shared__ int sel_chunk;
    __shared__ unsigned rem;

    int t = threadIdx.x, lane = t & 31, w = t >> 5;
    // chunk sums (coalesced per warp), chunk c covers bins [c*256, c*256+256)
    for (int s = w; s < 256; s += 8) {
        unsigned v = 0;
#pragma unroll
        for (int i2 = 0; i2 < 8; i2++) v += h[s * 256 + i2 * 32 + lane];
#pragma unroll
        for (int o = 16; o; o >>= 1) v += __shfl_xor_sync(0xffffffffu, v, o);
        if (lane == 0) chunk[s] = v;
    }
    __syncthreads();
    if (t == 0) {
        unsigned cum = 0;
        int c = 255;
        for (; c > 0; c--) {
            if (cum + chunk[c] >= target) break;
            cum += chunk[c];
        }
        sel_chunk = c;
        rem = target - cum;  // rem-th largest within chunk c (1-indexed)
    }
    __syncthreads();
    sbin[t] = h[sel_chunk * 256 + t];
    __syncthreads();
    if (t == 0) {
        unsigned cum = 0;
        int j = 255;
        unsigned r = rem;
        for (; j > 0; j--) {
            if (cum + sbin[j] >= r) break;
            cum += sbin[j];
        }
        unsigned bin = (unsigned)(sel_chunk * 256 + j);
        unsigned r2 = r - cum;
        if (level == 1) {
            g_bucket1[b] = bin;
            g_rank1[b] = r2;
        } else {
            g_kthkey[b] = (g_bucket1[b] << 16) | bin;
        }
    }
}

__global__ void __launch_bounds__(TPB) main_kernel(
    const float4* __restrict__ feats4,
    const float* __restrict__ scores,
    const int* __restrict__ bids,
    const float* __restrict__ w_reg,
    const float* __restrict__ w_cls,
    const float* __restrict__ b_cls,
    const float* __restrict__ scale,
    float4* __restrict__ out4,  // row stride 6 float4 (24 floats)
    int N) {
    __shared__ float sw[256 * 24];   // [k][j]: j<6 w_reg, j>=6 w_cls
    __shared__ int list[TPB * PPT];
    __shared__ int cnt;
    __shared__ float sb[24];         // constant row: 1.0 x6, b_cls x18
    __shared__ unsigned skey[MAXB];

    int t = threadIdx.x;
    if (t == 0) cnt = 0;
    if (t < MAXB) skey[t] = g_kthkey[t];
    if (t < 24) sb[t] = (t < 6) ? 1.0f : b_cls[t - 6];
    for (int i = t; i < 256 * 24; i += TPB) {
        int k = i / 24, j = i % 24;
        sw[i] = (j < 6) ? w_reg[k * 6 + j] : w_cls[k * 18 + (j - 6)];
    }
    float sc = scale[0];
    __syncthreads();

    long long base = (long long)blockIdx.x * (TPB * PPT);
#pragma unroll
    for (int it = 0; it < PPT; it++) {
        int p = (int)(base + (long long)it * TPB + t);
        bool keep = false;
        if (p < N) {
            unsigned b = (unsigned)bids[p];
            unsigned key = f2key(scores[p]);
            keep = (b < MAXB) && (key >= skey[b]);
            if (!keep) {
                float4* o = out4 + (size_t)p * 6;
                o[0] = make_float4(1.f, 1.f, 1.f, 1.f);
                o[1] = make_float4(1.f, 1.f, sb[6], sb[7]);
                o[2] = make_float4(sb[8], sb[9], sb[10], sb[11]);
                o[3] = make_float4(sb[12], sb[13], sb[14], sb[15]);
                o[4] = make_float4(sb[16], sb[17], sb[18], sb[19]);
                o[5] = make_float4(sb[20], sb[21], sb[22], sb[23]);
            }
        }
        unsigned bal = __ballot_sync(0xffffffffu, keep);
        int nk = __popc(bal);
        if (nk) {
            int lb = 0;
            if ((t & 31) == 0) lb = atomicAdd(&cnt, nk);
            lb = __shfl_sync(0xffffffffu, lb, 0);
            if (keep) list[lb + __popc(bal & ((1u << (t & 31)) - 1u))] = p;
        }
    }
    __syncthreads();

    int n = cnt;
    const float4* sw4 = reinterpret_cast<const float4*>(sw);
    for (int i = t; i < n; i += TPB) {
        int p = list[i];
        const float4* f = feats4 + (size_t)p * 64;
        float acc[24];
#pragma unroll
        for (int j = 0; j < 24; j++) acc[j] = 0.f;
#pragma unroll 4
        for (int k4 = 0; k4 < 64; k4++) {
            float4 x = __ldg(&f[k4]);
#pragma unroll
            for (int s = 0; s < 4; s++) {
                float xs = (s == 0) ? x.x : (s == 1) ? x.y : (s == 2) ? x.z : x.w;
                const float4* wrow = sw4 + (k4 * 4 + s) * 6;
#pragma unroll
                for (int jj = 0; jj < 6; jj++) {
                    float4 wv = wrow[jj];
                    acc[jj * 4 + 0] = fmaf(xs, wv.x, acc[jj * 4 + 0]);
                    acc[jj * 4 + 1] = fmaf(xs, wv.y, acc[jj * 4 + 1]);
                    acc[jj * 4 + 2] = fmaf(xs, wv.z, acc[jj * 4 + 2]);
                    acc[jj * 4 + 3] = fmaf(xs, wv.w, acc[jj * 4 + 3]);
                }
            }
        }
        float r[24];
#pragma unroll
        for (int j = 0; j < 6; j++) r[j] = expf(sc * acc[j]);
#pragma unroll
        for (int j = 6; j < 24; j++) r[j] = acc[j] + sb[j];
        float4* o = out4 + (size_t)p * 6;
#pragma unroll
        for (int jj = 0; jj < 6; jj++)
            o[jj] = make_float4(r[jj * 4], r[jj * 4 + 1], r[jj * 4 + 2], r[jj * 4 + 3]);
    }
}

extern "C" void kernel_launch(void* const* d_in, const int* in_sizes, int n_in,
                              void* d_out, int out_size) {
    const float* feats  = (const float*)d_in[0];
    const float* scores = (const float*)d_in[1];
    const float* w_reg  = (const float*)d_in[2];
    const float* w_cls  = (const float*)d_in[3];
    const float* b_cls  = (const float*)d_in[4];
    const float* scale  = (const float*)d_in[5];
    const int*   bids   = (const int*)d_in[6];
    const int*   nb     = (n_in > 7) ? (const int*)d_in[7] : nullptr;
    const int*   kp     = (n_in > 8) ? (const int*)d_in[8] : nullptr;
    int N = in_sizes[0] / 256;

    zero_kernel<<<(MAXB * NBIN / 4) / 256, 256>>>();
    hist1_kernel<<<(N + 255) / 256, 256>>>(scores, bids, N);
    scan_kernel<<<MAXB, 256>>>(nb, kp, 1);
    hist2_kernel<<<(N + 255) / 256, 256>>>(scores, bids, N);
    scan_kernel<<<MAXB, 256>>>(nb, kp, 2);
    int nblk = (N + TPB * PPT - 1) / (TPB * PPT);
    main_kernel<<<nblk, TPB>>>((const float4*)feats, scores, bids,
                               w_reg, w_cls, b_cls, scale,
                               (float4*)d_out, N);
}

// round 2
// speedup vs baseline: 1.1885x; 1.1885x over previous
#include <cuda_runtime.h>
#include <cstdint>
#include <math.h>

#define NBIN 65536
#define MAXB 16
#define NMAX 262144

#define GTPB 128
#define GP 4
#define GTILE (GTPB * GP)   // 512 points per CTA tile

// ---- device scratch (no allocation allowed) ----
__device__ unsigned g_hist1[MAXB * NBIN];
__device__ unsigned g_hist2[MAXB * NBIN];
__device__ unsigned g_bucket1[MAXB];
__device__ unsigned g_rank1[MAXB];
__device__ unsigned g_kthkey[MAXB];
__device__ int g_list[NMAX];
__device__ int g_cnt;

__device__ __forceinline__ unsigned f2key(float s) {
    unsigned u = __float_as_uint(s);
    return (u & 0x80000000u) ? ~u : (u | 0x80000000u);
}

__device__ __forceinline__ unsigned long long ffma2(
    unsigned long long a, unsigned long long b, unsigned long long c) {
    unsigned long long d;
    asm("fma.rn.f32x2 %0, %1, %2, %3;" : "=l"(d) : "l"(a), "l"(b), "l"(c));
    return d;
}
__device__ __forceinline__ unsigned long long pack2(float x) {
    unsigned long long d;
    asm("mov.b64 %0, {%1, %1};" : "=l"(d) : "f"(x));
    return d;
}
__device__ __forceinline__ void unpack2(unsigned long long v, float& lo, float& hi) {
    asm("mov.b64 {%0, %1}, %2;" : "=f"(lo), "=f"(hi) : "l"(v));
}

__global__ void zero_kernel() {
    unsigned i = blockIdx.x * blockDim.x + threadIdx.x;  // covers MAXB*NBIN/4 per hist
    uint4 z = make_uint4(0u, 0u, 0u, 0u);
    reinterpret_cast<uint4*>(g_hist1)[i] = z;
    reinterpret_cast<uint4*>(g_hist2)[i] = z;
    if (i == 0) g_cnt = 0;
}

__global__ void hist1_kernel(const float4* __restrict__ scores4,
                             const int4* __restrict__ bids4, int N4) {
    int i = blockIdx.x * blockDim.x + threadIdx.x;
    if (i >= N4) return;
    float4 s = scores4[i];
    int4 b = bids4[i];
    atomicAdd(&g_hist1[(unsigned)b.x * NBIN + (f2key(s.x) >> 16)], 1u);
    atomicAdd(&g_hist1[(unsigned)b.y * NBIN + (f2key(s.y) >> 16)], 1u);
    atomicAdd(&g_hist1[(unsigned)b.z * NBIN + (f2key(s.z) >> 16)], 1u);
    atomicAdd(&g_hist1[(unsigned)b.w * NBIN + (f2key(s.w) >> 16)], 1u);
}

__global__ void hist2_kernel(const float4* __restrict__ scores4,
                             const int4* __restrict__ bids4, int N4) {
    int i = blockIdx.x * blockDim.x + threadIdx.x;
    if (i >= N4) return;
    float4 s = scores4[i];
    int4 b = bids4[i];
    unsigned k0 = f2key(s.x), k1 = f2key(s.y), k2 = f2key(s.z), k3 = f2key(s.w);
    if ((k0 >> 16) == g_bucket1[b.x]) atomicAdd(&g_hist2[(unsigned)b.x * NBIN + (k0 & 0xFFFFu)], 1u);
    if ((k1 >> 16) == g_bucket1[b.y]) atomicAdd(&g_hist2[(unsigned)b.y * NBIN + (k1 & 0xFFFFu)], 1u);
    if ((k2 >> 16) == g_bucket1[b.z]) atomicAdd(&g_hist2[(unsigned)b.z * NBIN + (k2 & 0xFFFFu)], 1u);
    if ((k3 >> 16) == g_bucket1[b.w]) atomicAdd(&g_hist2[(unsigned)b.w * NBIN + (k3 & 0xFFFFu)], 1u);
}

// level 1: 16-bit bucket containing the k-th largest + residual rank.
// level 2: exact low-16 bits -> full 32-bit kth key.
__global__ void scan_kernel(const int* nb_ptr, const int* k_ptr, int level) {
    int B = nb_ptr ? *nb_ptr : 8;
    int b = blockIdx.x;
    if (b >= B) return;
    const unsigned* h = (level == 1 ? g_hist1 : g_hist2) + (size_t)b * NBIN;
    unsigned target = (level == 1) ? (unsigned)(k_ptr ? *k_ptr : 8192) : g_rank1[b];

    __shared__ unsigned chunk[256];
    __shared__ unsigned sbin[256];
    __shared__ int sel_chunk;
    __shared__ unsigned rem;

    int t = threadIdx.x, lane = t & 31, w = t >> 5;
    for (int s = w; s < 256; s += 8) {
        unsigned v = 0;
#pragma unroll
        for (int i2 = 0; i2 < 8; i2++) v += h[s * 256 + i2 * 32 + lane];
#pragma unroll
        for (int o = 16; o; o >>= 1) v += __shfl_xor_sync(0xffffffffu, v, o);
        if (lane == 0) chunk[s] = v;
    }
    __syncthreads();
    if (t == 0) {
        unsigned cum = 0;
        int c = 255;
        for (; c > 0; c--) {
            if (cum + chunk[c] >= target) break;
            cum += chunk[c];
        }
        sel_chunk = c;
        rem = target - cum;
    }
    __syncthreads();
    sbin[t] = h[sel_chunk * 256 + t];
    __syncthreads();
    if (t == 0) {
        unsigned cum = 0;
        int j = 255;
        unsigned r = rem;
        for (; j > 0; j--) {
            if (cum + sbin[j] >= r) break;
            cum += sbin[j];
        }
        unsigned bin = (unsigned)(sel_chunk * 256 + j);
        if (level == 1) {
            g_bucket1[b] = bin;
            g_rank1[b] = r - cum;
        } else {
            g_kthkey[b] = (g_bucket1[b] << 16) | bin;
        }
    }
}

// mask + fill pruned rows with constant + compact kept indices globally
__global__ void __launch_bounds__(256) compact_fill_kernel(
    const float* __restrict__ scores,
    const int* __restrict__ bids,
    const float* __restrict__ b_cls,
    float4* __restrict__ out4, int N) {
    __shared__ float sb[24];
    __shared__ unsigned skey[MAXB];
    int t = threadIdx.x;
    if (t < MAXB) skey[t] = g_kthkey[t];
    if (t < 24) sb[t] = (t < 6) ? 1.0f : b_cls[t - 6];
    __syncthreads();

    long long base = (long long)blockIdx.x * 1024;
#pragma unroll
    for (int it = 0; it < 4; it++) {
        int p = (int)(base + it * 256 + t);
        bool keep = false;
        if (p < N) {
            unsigned b = (unsigned)bids[p];
            unsigned key = f2key(scores[p]);
            keep = (b < MAXB) && (key >= skey[b]);
            if (!keep) {
                float4* o = out4 + (size_t)p * 6;
                o[0] = make_float4(1.f, 1.f, 1.f, 1.f);
                o[1] = make_float4(1.f, 1.f, sb[6], sb[7]);
                o[2] = make_float4(sb[8], sb[9], sb[10], sb[11]);
                o[3] = make_float4(sb[12], sb[13], sb[14], sb[15]);
                o[4] = make_float4(sb[16], sb[17], sb[18], sb[19]);
                o[5] = make_float4(sb[20], sb[21], sb[22], sb[23]);
            }
        }
        unsigned bal = __ballot_sync(0xffffffffu, keep);
        int nk = __popc(bal);
        if (nk) {
            int gb = 0;
            if ((t & 31) == 0) gb = atomicAdd(&g_cnt, nk);
            gb = __shfl_sync(0xffffffffu, gb, 0);
            if (keep) g_list[gb + __popc(bal & ((1u << (t & 31)) - 1u))] = p;
        }
    }
}

// balanced GEMV over compacted kept points; weights in smem, FFMA2-packed.
__global__ void __launch_bounds__(GTPB, 1) gemv_kernel(
    const float4* __restrict__ feats4,
    const float* __restrict__ w_reg,
    const float* __restrict__ w_cls,
    const float* __restrict__ b_cls,
    const float* __restrict__ scale,
    float4* __restrict__ out4) {
    __shared__ __align__(16) float sw[256 * 24];  // [k][j]
    __shared__ float sb[24];

    int t = threadIdx.x;
    if (t < 24) sb[t] = (t < 6) ? 1.0f : b_cls[t - 6];
    for (int i = t; i < 256 * 24; i += GTPB) {
        int k = i / 24, j = i % 24;
        sw[i] = (j < 6) ? w_reg[k * 6 + j] : w_cls[k * 18 + (j - 6)];
    }
    float sc = scale[0];
    __syncthreads();

    int T = g_cnt;
    const ulonglong2* swp = reinterpret_cast<const ulonglong2*>(sw);  // 6 per k

    for (int tile = blockIdx.x; tile * GTILE < T; tile += gridDim.x) {
        int base = tile * GTILE + t;
        const float4* fp[GP];
        bool v[GP];
#pragma unroll
        for (int p = 0; p < GP; p++) {
            int ii = base + p * GTPB;
            v[p] = ii < T;
            int idx = v[p] ? g_list[ii] : 0;
            fp[p] = feats4 + (size_t)idx * 64;
        }

        unsigned long long acc[GP][12];
#pragma unroll
        for (int p = 0; p < GP; p++)
#pragma unroll
            for (int j = 0; j < 12; j++) acc[p][j] = 0ull;

        float4 xb[GP];
#pragma unroll
        for (int p = 0; p < GP; p++) xb[p] = __ldg(&fp[p][0]);

        for (int k4 = 0; k4 < 64; k4++) {
            float4 xn[GP];
            int kn = (k4 < 63) ? (k4 + 1) : 63;
#pragma unroll
            for (int p = 0; p < GP; p++) xn[p] = __ldg(&fp[p][kn]);

#pragma unroll
            for (int s = 0; s < 4; s++) {
                int k = k4 * 4 + s;
                unsigned long long xx[GP];
#pragma unroll
                for (int p = 0; p < GP; p++) {
                    float xs = (s == 0) ? xb[p].x : (s == 1) ? xb[p].y
                             : (s == 2) ? xb[p].z : xb[p].w;
                    xx[p] = pack2(xs);
                }
#pragma unroll
                for (int q = 0; q < 6; q++) {
                    ulonglong2 w = swp[k * 6 + q];
#pragma unroll
                    for (int p = 0; p < GP; p++) {
                        acc[p][2 * q]     = ffma2(xx[p], w.x, acc[p][2 * q]);
                        acc[p][2 * q + 1] = ffma2(xx[p], w.y, acc[p][2 * q + 1]);
                    }
                }
            }
#pragma unroll
            for (int p = 0; p < GP; p++) xb[p] = xn[p];
        }

#pragma unroll
        for (int p = 0; p < GP; p++) {
            if (!v[p]) continue;
            int idx = (int)((fp[p] - feats4) / 64);
            float r[24];
#pragma unroll
            for (int j = 0; j < 12; j++) unpack2(acc[p][j], r[2 * j], r[2 * j + 1]);
#pragma unroll
            for (int j = 0; j < 6; j++) r[j] = expf(sc * r[j]);
#pragma unroll
            for (int j = 6; j < 24; j++) r[j] = r[j] + sb[j];
            float4* o = out4 + (size_t)idx * 6;
#pragma unroll
            for (int jj = 0; jj < 6; jj++)
                o[jj] = make_float4(r[4 * jj], r[4 * jj + 1], r[4 * jj + 2], r[4 * jj + 3]);
        }
    }
}

extern "C" void kernel_launch(void* const* d_in, const int* in_sizes, int n_in,
                              void* d_out, int out_size) {
    const float* feats  = (const float*)d_in[0];
    const float* scores = (const float*)d_in[1];
    const float* w_reg  = (const float*)d_in[2];
    const float* w_cls  = (const float*)d_in[3];
    const float* b_cls  = (const float*)d_in[4];
    const float* scale  = (const float*)d_in[5];
    const int*   bids   = (const int*)d_in[6];
    const int*   nb     = (n_in > 7) ? (const int*)d_in[7] : nullptr;
    const int*   kp     = (n_in > 8) ? (const int*)d_in[8] : nullptr;
    int N = in_sizes[0] / 256;
    int N4 = N / 4;

    zero_kernel<<<(MAXB * NBIN / 4) / 256, 256>>>();
    hist1_kernel<<<(N4 + 255) / 256, 256>>>((const float4*)scores, (const int4*)bids, N4);
    scan_kernel<<<MAXB, 256>>>(nb, kp, 1);
    hist2_kernel<<<(N4 + 255) / 256, 256>>>((const float4*)scores, (const int4*)bids, N4);
    scan_kernel<<<MAXB, 256>>>(nb, kp, 2);
    compact_fill_kernel<<<(N + 1023) / 1024, 256>>>(scores, bids, b_cls, (float4*)d_out, N);
    gemv_kernel<<<128, GTPB>>>((const float4*)feats, w_reg, w_cls, b_cls, scale,
                               (float4*)d_out);
}

// round 3
// speedup vs baseline: 1.4728x; 1.2392x over previous
#include <cuda_runtime.h>
#include <cstdint>
#include <math.h>

#define NBIN 65536
#define MAXB 16
#define NMAX 262144

#define GTPB 256
#define GP 2
#define GTILE (GTPB * GP)   // 512 points per CTA tile

// ---- device scratch (no allocation allowed) ----
__device__ unsigned g_hist1[MAXB * NBIN];
__device__ unsigned g_hist2[MAXB * NBIN];
__device__ unsigned g_bucket1[MAXB];
__device__ unsigned g_rank1[MAXB];
__device__ unsigned g_kthkey[MAXB];
__device__ int g_list[NMAX];
__device__ int g_cnt;

__device__ __forceinline__ unsigned f2key(float s) {
    unsigned u = __float_as_uint(s);
    return (u & 0x80000000u) ? ~u : (u | 0x80000000u);
}

__device__ __forceinline__ unsigned long long ffma2(
    unsigned long long a, unsigned long long b, unsigned long long c) {
    unsigned long long d;
    asm("fma.rn.f32x2 %0, %1, %2, %3;" : "=l"(d) : "l"(a), "l"(b), "l"(c));
    return d;
}
__device__ __forceinline__ unsigned long long pack2(float x) {
    unsigned long long d;
    asm("mov.b64 %0, {%1, %1};" : "=l"(d) : "f"(x));
    return d;
}
__device__ __forceinline__ void unpack2(unsigned long long v, float& lo, float& hi) {
    asm("mov.b64 {%0, %1}, %2;" : "=f"(lo), "=f"(hi) : "l"(v));
}
__device__ __forceinline__ float getc(const float4& v, int s) {
    return (s == 0) ? v.x : (s == 1) ? v.y : (s == 2) ? v.z : v.w;
}

__global__ void zero_kernel() {
    unsigned i = blockIdx.x * blockDim.x + threadIdx.x;
    uint4 z = make_uint4(0u, 0u, 0u, 0u);
    reinterpret_cast<uint4*>(g_hist1)[i] = z;
    reinterpret_cast<uint4*>(g_hist2)[i] = z;
    if (i == 0) g_cnt = 0;
}

__global__ void hist1_kernel(const float* __restrict__ scores,
                             const int* __restrict__ bids, int N) {
    int i = blockIdx.x * blockDim.x + threadIdx.x;
    if (i >= N) return;
    unsigned b = (unsigned)bids[i];
    if (b >= MAXB) return;
    atomicAdd(&g_hist1[b * NBIN + (f2key(scores[i]) >> 16)], 1u);
}

__global__ void hist2_kernel(const float* __restrict__ scores,
                             const int* __restrict__ bids, int N) {
    int i = blockIdx.x * blockDim.x + threadIdx.x;
    if (i >= N) return;
    unsigned b = (unsigned)bids[i];
    if (b >= MAXB) return;
    unsigned key = f2key(scores[i]);
    if ((key >> 16) == g_bucket1[b])
        atomicAdd(&g_hist2[b * NBIN + (key & 0xFFFFu)], 1u);
}

// parallel suffix-scan select: one CTA per batch.
// level 1: 16-bit bucket holding the k-th largest + residual rank.
// level 2: exact low 16 bits -> full 32-bit kth key.
__global__ void scan_kernel(const int* nb_ptr, const int* k_ptr, int level) {
    int B = nb_ptr ? *nb_ptr : 8;
    if (B < 1 || B > MAXB) B = 8;
    int b = blockIdx.x;
    if (b >= B) return;
    const unsigned* h = (level == 1 ? g_hist1 : g_hist2) + (size_t)b * NBIN;
    unsigned target = (level == 1) ? (unsigned)(k_ptr ? *k_ptr : 8192) : g_rank1[b];

    __shared__ unsigned suf[257];
    __shared__ unsigned chunk[256];
    __shared__ int s_sel;
    __shared__ unsigned s_rem;

    int t = threadIdx.x, lane = t & 31, w = t >> 5;

    // chunk sums: chunk c covers bins [c*256, c*256+256)
    for (int s = w; s < 256; s += 8) {
        unsigned v = 0;
#pragma unroll
        for (int i2 = 0; i2 < 8; i2++) v += h[s * 256 + i2 * 32 + lane];
#pragma unroll
        for (int o = 16; o; o >>= 1) v += __shfl_xor_sync(0xffffffffu, v, o);
        if (lane == 0) chunk[s] = v;
    }
    __syncthreads();

    // ---- stage A: suffix scan over chunk sums ----
    suf[t] = chunk[t];
    if (t == 0) suf[256] = 0;
    __syncthreads();
#pragma unroll
    for (int off = 1; off < 256; off <<= 1) {
        unsigned add = suf[(t + off > 256) ? 256 : (t + off)];
        __syncthreads();
        suf[t] += add;
        __syncthreads();
    }
    if (suf[t] >= target && suf[t + 1] < target) {
        s_sel = t;
        s_rem = target - suf[t + 1];
    }
    __syncthreads();
    int sel = s_sel;
    unsigned rem = s_rem;
    __syncthreads();

    // ---- stage B: suffix scan over the 256 bins of the selected chunk ----
    suf[t] = h[sel * 256 + t];
    if (t == 0) suf[256] = 0;
    __syncthreads();
#pragma unroll
    for (int off = 1; off < 256; off <<= 1) {
        unsigned add = suf[(t + off > 256) ? 256 : (t + off)];
        __syncthreads();
        suf[t] += add;
        __syncthreads();
    }
    if (suf[t] >= rem && suf[t + 1] < rem) {
        unsigned bin = (unsigned)(sel * 256 + t);
        if (level == 1) {
            g_bucket1[b] = bin;
            g_rank1[b] = rem - suf[t + 1];
        } else {
            g_kthkey[b] = (g_bucket1[b] << 16) | bin;
        }
    }
}

// mask + fill pruned rows with constant + compact kept indices globally
__global__ void __launch_bounds__(256) compact_fill_kernel(
    const float* __restrict__ scores,
    const int* __restrict__ bids,
    const float* __restrict__ b_cls,
    float4* __restrict__ out4, int N) {
    __shared__ float sb[24];
    __shared__ unsigned skey[MAXB];
    int t = threadIdx.x;
    if (t < MAXB) skey[t] = g_kthkey[t];
    if (t < 24) sb[t] = (t < 6) ? 1.0f : b_cls[t - 6];
    __syncthreads();

    long long base = (long long)blockIdx.x * 1024;
#pragma unroll
    for (int it = 0; it < 4; it++) {
        int p = (int)(base + it * 256 + t);
        bool keep = false;
        if (p < N) {
            unsigned b = (unsigned)bids[p];
            unsigned key = f2key(scores[p]);
            keep = (b < MAXB) && (key >= skey[b]);
            if (!keep) {
                float4* o = out4 + (size_t)p * 6;
                o[0] = make_float4(1.f, 1.f, 1.f, 1.f);
                o[1] = make_float4(1.f, 1.f, sb[6], sb[7]);
                o[2] = make_float4(sb[8], sb[9], sb[10], sb[11]);
                o[3] = make_float4(sb[12], sb[13], sb[14], sb[15]);
                o[4] = make_float4(sb[16], sb[17], sb[18], sb[19]);
                o[5] = make_float4(sb[20], sb[21], sb[22], sb[23]);
            }
        }
        unsigned bal = __ballot_sync(0xffffffffu, keep);
        int nk = __popc(bal);
        if (nk) {
            int gb = 0;
            if ((t & 31) == 0) gb = atomicAdd(&g_cnt, nk);
            gb = __shfl_sync(0xffffffffu, gb, 0);
            if (keep) g_list[gb + __popc(bal & ((1u << (t & 31)) - 1u))] = p;
        }
    }
}

// balanced GEMV over compacted kept points.
// 256 thr/CTA (2 warps/SMSP), 2 pts/thread, double-buffered 16-k chunks (MLP=8).
__global__ void __launch_bounds__(GTPB, 1) gemv_kernel(
    const float4* __restrict__ feats4,
    const float* __restrict__ w_reg,
    const float* __restrict__ w_cls,
    const float* __restrict__ b_cls,
    const float* __restrict__ scale,
    float4* __restrict__ out4) {
    __shared__ __align__(16) float sw[256 * 24];  // [k][j]
    __shared__ float sb[24];

    int t = threadIdx.x;
    if (t < 24) sb[t] = (t < 6) ? 1.0f : b_cls[t - 6];
    for (int i = t; i < 256 * 24; i += GTPB) {
        int k = i / 24, j = i % 24;
        sw[i] = (j < 6) ? w_reg[k * 6 + j] : w_cls[k * 18 + (j - 6)];
    }
    float sc = scale[0];
    __syncthreads();

    int T = g_cnt;
    const ulonglong2* swp = reinterpret_cast<const ulonglong2*>(sw);  // 6 per k

    for (long long tb = (long long)blockIdx.x * GTILE; tb < T;
         tb += (long long)gridDim.x * GTILE) {
        int i0 = (int)tb + t;
        int i1 = i0 + GTPB;
        bool v0 = i0 < T, v1 = i1 < T;
        int idx0 = v0 ? g_list[i0] : 0;
        int idx1 = v1 ? g_list[i1] : 0;
        const float4* f0 = feats4 + (size_t)idx0 * 64;
        const float4* f1 = feats4 + (size_t)idx1 * 64;

        unsigned long long acc0[12], acc1[12];
#pragma unroll
        for (int j = 0; j < 12; j++) { acc0[j] = 0ull; acc1[j] = 0ull; }

        float4 c0[4], c1[4];
#pragma unroll
        for (int q = 0; q < 4; q++) { c0[q] = __ldcs(f0 + q); c1[q] = __ldcs(f1 + q); }

        for (int ch = 0; ch < 16; ch++) {
            float4 n0[4], n1[4];
            int nb = (ch < 15) ? (ch + 1) * 4 : 60;
#pragma unroll
            for (int q = 0; q < 4; q++) {
                n0[q] = __ldcs(f0 + nb + q);
                n1[q] = __ldcs(f1 + nb + q);
            }
#pragma unroll
            for (int q = 0; q < 4; q++) {
#pragma unroll
                for (int s = 0; s < 4; s++) {
                    int k = ch * 16 + q * 4 + s;
                    unsigned long long x0 = pack2(getc(c0[q], s));
                    unsigned long long x1 = pack2(getc(c1[q], s));
#pragma unroll
                    for (int j = 0; j < 6; j++) {
                        ulonglong2 w = swp[k * 6 + j];
                        acc0[2 * j]     = ffma2(x0, w.x, acc0[2 * j]);
                        acc0[2 * j + 1] = ffma2(x0, w.y, acc0[2 * j + 1]);
                        acc1[2 * j]     = ffma2(x1, w.x, acc1[2 * j]);
                        acc1[2 * j + 1] = ffma2(x1, w.y, acc1[2 * j + 1]);
                    }
                }
            }
#pragma unroll
            for (int q = 0; q < 4; q++) { c0[q] = n0[q]; c1[q] = n1[q]; }
        }

#pragma unroll
        for (int p = 0; p < GP; p++) {
            bool vv = (p == 0) ? v0 : v1;
            if (!vv) continue;
            int idx = (p == 0) ? idx0 : idx1;
            unsigned long long* acc = (p == 0) ? acc0 : acc1;
            float r[24];
#pragma unroll
            for (int j = 0; j < 12; j++) unpack2(acc[j], r[2 * j], r[2 * j + 1]);
#pragma unroll
            for (int j = 0; j < 6; j++) r[j] = expf(sc * r[j]);
#pragma unroll
            for (int j = 6; j < 24; j++) r[j] = r[j] + sb[j];
            float4* o = out4 + (size_t)idx * 6;
#pragma unroll
            for (int jj = 0; jj < 6; jj++)
                o[jj] = make_float4(r[4 * jj], r[4 * jj + 1], r[4 * jj + 2], r[4 * jj + 3]);
        }
    }
}

extern "C" void kernel_launch(void* const* d_in, const int* in_sizes, int n_in,
                              void* d_out, int out_size) {
    const float* feats  = (const float*)d_in[0];
    const float* scores = (const float*)d_in[1];
    const float* w_reg  = (const float*)d_in[2];
    const float* w_cls  = (const float*)d_in[3];
    const float* b_cls  = (const float*)d_in[4];
    const float* scale  = (const float*)d_in[5];
    const int*   bids   = (const int*)d_in[6];
    const int*   nb     = (n_in > 7) ? (const int*)d_in[7] : nullptr;
    const int*   kp     = (n_in > 8) ? (const int*)d_in[8] : nullptr;
    int N = in_sizes[0] / 256;

    zero_kernel<<<(MAXB * NBIN / 4) / 256, 256>>>();
    hist1_kernel<<<(N + 255) / 256, 256>>>(scores, bids, N);
    scan_kernel<<<MAXB, 256>>>(nb, kp, 1);
    hist2_kernel<<<(N + 255) / 256, 256>>>(scores, bids, N);
    scan_kernel<<<MAXB, 256>>>(nb, kp, 2);
    compact_fill_kernel<<<(N + 1023) / 1024, 256>>>(scores, bids, b_cls, (float4*)d_out, N);
    gemv_kernel<<<128, GTPB>>>((const float4*)feats, w_reg, w_cls, b_cls, scale,
                               (float4*)d_out);
}